// round 1
// baseline (speedup 1.0000x reference)
#include <cuda_runtime.h>

#define NV   514
#define SDIM 512
#define MROWS 65536
#define EPSF 1e-16f

// R = Q^T, row-major [SDIM][SDIM]; scratch via device globals (no allocs allowed)
__device__ float g_R[SDIM * SDIM];
__device__ float g_c[NV];

// ---------------------------------------------------------------------------
// Kernel 1: c_k = 2 / (||v_k||^2 + eps)
// ---------------------------------------------------------------------------
__global__ void compute_c_kernel(const float* __restrict__ v) {
    const int k = blockIdx.x;
    const int t = threadIdx.x;          // 128 threads
    const float* vk = v + k * SDIM;
    float s = 0.f;
    #pragma unroll
    for (int i = t; i < SDIM; i += 128) {
        float a = vk[i];
        s = fmaf(a, a, s);
    }
    #pragma unroll
    for (int o = 16; o > 0; o >>= 1)
        s += __shfl_xor_sync(0xffffffffu, s, o);
    __shared__ float red[4];
    if ((t & 31) == 0) red[t >> 5] = s;
    __syncthreads();
    if (t == 0) {
        float tot = red[0] + red[1] + red[2] + red[3];
        g_c[k] = 2.0f / (tot + EPSF);
    }
}

// ---------------------------------------------------------------------------
// Kernel 2: build R = M_{N-1} ... M_0  (columns independent)
// One warp per column j. Column vector r kept in registers (16 floats/lane
// as 4 float4). For each k: r -= c_k * (v_k . r) * v_k
// Element mapping: lane holds indices i = m*128 + lane*4 + q  (m=0..3,q=0..3)
// ---------------------------------------------------------------------------
__global__ __launch_bounds__(256) void build_R_kernel(const float* __restrict__ v) {
    __shared__ float sc[NV];
    for (int i = threadIdx.x; i < NV; i += blockDim.x) sc[i] = g_c[i];
    __syncthreads();

    const int warp = (blockIdx.x * blockDim.x + threadIdx.x) >> 5;
    const int lane = threadIdx.x & 31;
    if (warp >= SDIM) return;
    const int j = warp;

    float4 r0 = make_float4(0.f, 0.f, 0.f, 0.f);
    float4 r1 = r0, r2 = r0, r3 = r0;
    {   // r = e_j
        const int m = j >> 7, rem = j & 127;
        if ((rem >> 2) == lane) {
            float* p = (m == 0) ? (float*)&r0 : (m == 1) ? (float*)&r1
                     : (m == 2) ? (float*)&r2 : (float*)&r3;
            p[rem & 3] = 1.0f;
        }
    }

    const float4* v4 = (const float4*)v;   // each vector = 128 float4
    for (int k = 0; k < NV; ++k) {
        const float4* vk = v4 + k * (SDIM / 4);
        const float4 a0 = vk[lane];
        const float4 a1 = vk[lane + 32];
        const float4 a2 = vk[lane + 64];
        const float4 a3 = vk[lane + 96];

        float d = 0.f;
        d = fmaf(a0.x, r0.x, d); d = fmaf(a0.y, r0.y, d);
        d = fmaf(a0.z, r0.z, d); d = fmaf(a0.w, r0.w, d);
        d = fmaf(a1.x, r1.x, d); d = fmaf(a1.y, r1.y, d);
        d = fmaf(a1.z, r1.z, d); d = fmaf(a1.w, r1.w, d);
        d = fmaf(a2.x, r2.x, d); d = fmaf(a2.y, r2.y, d);
        d = fmaf(a2.z, r2.z, d); d = fmaf(a2.w, r2.w, d);
        d = fmaf(a3.x, r3.x, d); d = fmaf(a3.y, r3.y, d);
        d = fmaf(a3.z, r3.z, d); d = fmaf(a3.w, r3.w, d);
        #pragma unroll
        for (int o = 16; o > 0; o >>= 1)
            d += __shfl_xor_sync(0xffffffffu, d, o);

        const float t = d * sc[k];
        r0.x = fmaf(-t, a0.x, r0.x); r0.y = fmaf(-t, a0.y, r0.y);
        r0.z = fmaf(-t, a0.z, r0.z); r0.w = fmaf(-t, a0.w, r0.w);
        r1.x = fmaf(-t, a1.x, r1.x); r1.y = fmaf(-t, a1.y, r1.y);
        r1.z = fmaf(-t, a1.z, r1.z); r1.w = fmaf(-t, a1.w, r1.w);
        r2.x = fmaf(-t, a2.x, r2.x); r2.y = fmaf(-t, a2.y, r2.y);
        r2.z = fmaf(-t, a2.z, r2.z); r2.w = fmaf(-t, a2.w, r2.w);
        r3.x = fmaf(-t, a3.x, r3.x); r3.y = fmaf(-t, a3.y, r3.y);
        r3.z = fmaf(-t, a3.z, r3.z); r3.w = fmaf(-t, a3.w, r3.w);
    }

    // store column j:  g_R[i * SDIM + j]
    const float4 rr[4] = {r0, r1, r2, r3};
    #pragma unroll
    for (int m = 0; m < 4; ++m) {
        const float* p = (const float*)&rr[m];
        #pragma unroll
        for (int q = 0; q < 4; ++q) {
            const int i = m * 128 + lane * 4 + q;
            g_R[i * SDIM + j] = p[q];
        }
    }
}

// ---------------------------------------------------------------------------
// Kernel 3: out = x @ R   (M=65536, K=512, N=512) fp32 SIMT 128x128x8 tiling
// 256 threads, each computes 8x8.
// ---------------------------------------------------------------------------
__global__ __launch_bounds__(256) void sgemm128_kernel(const float* __restrict__ A,
                                                       float* __restrict__ C) {
    __shared__ float As[8][128];   // As[k][m]
    __shared__ float Bs[8][128];   // Bs[k][n]

    const int tid = threadIdx.x;
    const int bm = blockIdx.y << 7;
    const int bn = blockIdx.x << 7;

    const int arow = tid >> 1;            // 0..127
    const int ak   = (tid & 1) << 2;      // 0 or 4
    const int bk   = tid >> 5;            // 0..7
    const int bc   = (tid & 31) << 2;     // 0..124

    const int ty = tid >> 4;              // 0..15
    const int tx = tid & 15;              // 0..15

    const float* Aptr = A + (size_t)(bm + arow) * SDIM + ak;
    const float* Bptr = g_R + bk * SDIM + bn + bc;

    float acc[8][8];
    #pragma unroll
    for (int i = 0; i < 8; ++i)
        #pragma unroll
        for (int jj = 0; jj < 8; ++jj) acc[i][jj] = 0.f;

    for (int k0 = 0; k0 < SDIM; k0 += 8) {
        const float4 av = *(const float4*)(Aptr + k0);
        const float4 bv = *(const float4*)(Bptr + (size_t)k0 * SDIM);
        __syncthreads();
        As[ak + 0][arow] = av.x;
        As[ak + 1][arow] = av.y;
        As[ak + 2][arow] = av.z;
        As[ak + 3][arow] = av.w;
        *(float4*)&Bs[bk][bc] = bv;
        __syncthreads();

        #pragma unroll
        for (int kk = 0; kk < 8; ++kk) {
            float a[8], b[8];
            const float4 a0 = *(const float4*)&As[kk][ty * 8];
            const float4 a1 = *(const float4*)&As[kk][ty * 8 + 4];
            const float4 b0 = *(const float4*)&Bs[kk][tx * 8];
            const float4 b1 = *(const float4*)&Bs[kk][tx * 8 + 4];
            a[0]=a0.x; a[1]=a0.y; a[2]=a0.z; a[3]=a0.w;
            a[4]=a1.x; a[5]=a1.y; a[6]=a1.z; a[7]=a1.w;
            b[0]=b0.x; b[1]=b0.y; b[2]=b0.z; b[3]=b0.w;
            b[4]=b1.x; b[5]=b1.y; b[6]=b1.z; b[7]=b1.w;
            #pragma unroll
            for (int i = 0; i < 8; ++i)
                #pragma unroll
                for (int jj = 0; jj < 8; ++jj)
                    acc[i][jj] = fmaf(a[i], b[jj], acc[i][jj]);
        }
    }

    #pragma unroll
    for (int i = 0; i < 8; ++i) {
        const size_t row = (size_t)(bm + ty * 8 + i);
        float* cp = C + row * SDIM + bn + tx * 8;
        float4 o0 = make_float4(acc[i][0], acc[i][1], acc[i][2], acc[i][3]);
        float4 o1 = make_float4(acc[i][4], acc[i][5], acc[i][6], acc[i][7]);
        *(float4*)(cp + 0) = o0;
        *(float4*)(cp + 4) = o1;
    }
}

// ---------------------------------------------------------------------------
extern "C" void kernel_launch(void* const* d_in, const int* in_sizes, int n_in,
                              void* d_out, int out_size) {
    const float* x = (const float*)d_in[0];        // [65536, 512]
    const float* v = (const float*)d_in[1];        // [514, 512, 1]
    float* out = (float*)d_out;                    // [65536, 512]

    compute_c_kernel<<<NV, 128>>>(v);
    build_R_kernel<<<(SDIM * 32 + 255) / 256, 256>>>(v);
    dim3 grid(SDIM / 128, MROWS / 128);
    sgemm128_kernel<<<grid, 256>>>(x, out);
}

// round 3
// speedup vs baseline: 1.7150x; 1.7150x over previous
#include <cuda_runtime.h>
#include <cuda_bf16.h>
#include <cstdint>

#define NV    514
#define SDIM  512
#define MROWS 65536
#define EPSF  1e-16f

// ---------------------------------------------------------------------------
// Device scratch. g_B holds R^T rows (= R columns) as bf16 hi/lo splits,
// PRE-SWIZZLED SMEM tile images:
//   [split(2)][ntile(2)][chunk(8)] blocks of 32768 B; each block is a
//   256(n-rows) x 64(k) bf16 tile, 128 B/row, SW128-swizzled.
// ---------------------------------------------------------------------------
__device__ __align__(16) unsigned char g_B[2 * 2 * 8 * 32768];
__device__ float g_c[NV];

#define SW128(b) ((b) ^ (((b) >> 3) & 0x70))

__device__ __forceinline__ uint32_t smem_u32(const void* p) {
    uint32_t a;
    asm("{ .reg .u64 t; cvta.to.shared.u64 t, %1; cvt.u32.u64 %0, t; }"
        : "=r"(a) : "l"(p));
    return a;
}

// ===========================================================================
// Kernel 1: c_k = 2 / (||v_k||^2 + eps)
// ===========================================================================
__global__ void compute_c_kernel(const float* __restrict__ v) {
    const int k = blockIdx.x;
    const int t = threadIdx.x;
    const float* vk = v + k * SDIM;
    float s = 0.f;
    for (int i = t; i < SDIM; i += 128) { float a = vk[i]; s = fmaf(a, a, s); }
    #pragma unroll
    for (int o = 16; o > 0; o >>= 1) s += __shfl_xor_sync(0xffffffffu, s, o);
    __shared__ float red[4];
    if ((t & 31) == 0) red[t >> 5] = s;
    __syncthreads();
    if (t == 0) g_c[k] = 2.0f / (red[0] + red[1] + red[2] + red[3] + EPSF);
}

// ===========================================================================
// Kernel 2: reflector chain -> rows of R^T, emitted as bf16 hi/lo into the
// pre-swizzled tile layout of g_B. One warp per column j.
// ===========================================================================
__global__ __launch_bounds__(256) void build_R_kernel(const float* __restrict__ v) {
    __shared__ float sc[NV];
    for (int i = threadIdx.x; i < NV; i += blockDim.x) sc[i] = g_c[i];
    __syncthreads();

    const int warp = (blockIdx.x * blockDim.x + threadIdx.x) >> 5;
    const int lane = threadIdx.x & 31;
    if (warp >= SDIM) return;
    const int j = warp;

    float r[16];
    #pragma unroll
    for (int i = 0; i < 16; ++i) r[i] = 0.f;
    {
        const int m = j >> 7;
        if (lane == ((j & 127) >> 2)) r[m * 4 + (j & 3)] = 1.0f;
    }

    const float4* v4 = (const float4*)v;
    float a[16], an[16];
    #pragma unroll
    for (int m = 0; m < 4; ++m) {
        float4 t = v4[m * 32 + lane];
        a[m*4+0]=t.x; a[m*4+1]=t.y; a[m*4+2]=t.z; a[m*4+3]=t.w;
    }

    for (int k = 0; k < NV; ++k) {
        float d0 = 0.f, d1 = 0.f, d2 = 0.f, d3 = 0.f;
        #pragma unroll
        for (int q = 0; q < 4; ++q) {
            d0 = fmaf(a[0*4+q], r[0*4+q], d0);
            d1 = fmaf(a[1*4+q], r[1*4+q], d1);
            d2 = fmaf(a[2*4+q], r[2*4+q], d2);
            d3 = fmaf(a[3*4+q], r[3*4+q], d3);
        }
        if (k + 1 < NV) {
            const float4* vn = v4 + (size_t)(k + 1) * 128;
            #pragma unroll
            for (int m = 0; m < 4; ++m) {
                float4 t = vn[m * 32 + lane];
                an[m*4+0]=t.x; an[m*4+1]=t.y; an[m*4+2]=t.z; an[m*4+3]=t.w;
            }
        }
        float d = (d0 + d1) + (d2 + d3);
        #pragma unroll
        for (int o = 16; o > 0; o >>= 1) d += __shfl_xor_sync(0xffffffffu, d, o);

        const float t = d * sc[k];
        #pragma unroll
        for (int i = 0; i < 16; ++i) r[i] = fmaf(-t, a[i], r[i]);
        #pragma unroll
        for (int i = 0; i < 16; ++i) a[i] = an[i];
    }

    const int ntile = j >> 8;
    const unsigned rowb = (unsigned)(j & 255) * 128u;
    #pragma unroll
    for (int m = 0; m < 4; ++m) {
        const int k0 = m * 128 + lane * 4;
        const int chunk = k0 >> 6;
        const unsigned off = rowb + (unsigned)((k0 & 63) * 2);
        const unsigned sw = SW128(off);

        __nv_bfloat16 h0 = __float2bfloat16(r[m*4+0]);
        __nv_bfloat16 h1 = __float2bfloat16(r[m*4+1]);
        __nv_bfloat16 h2 = __float2bfloat16(r[m*4+2]);
        __nv_bfloat16 h3 = __float2bfloat16(r[m*4+3]);
        float l0 = r[m*4+0] - __bfloat162float(h0);
        float l1 = r[m*4+1] - __bfloat162float(h1);
        float l2 = r[m*4+2] - __bfloat162float(h2);
        float l3 = r[m*4+3] - __bfloat162float(h3);
        __nv_bfloat162 hp0 = __halves2bfloat162(h0, h1);
        __nv_bfloat162 hp1 = __halves2bfloat162(h2, h3);
        __nv_bfloat162 lp0 = __floats2bfloat162_rn(l0, l1);
        __nv_bfloat162 lp1 = __floats2bfloat162_rn(l2, l3);

        uint2 H = make_uint2(*(uint32_t*)&hp0, *(uint32_t*)&hp1);
        uint2 L = make_uint2(*(uint32_t*)&lp0, *(uint32_t*)&lp1);
        *(uint2*)(g_B + (((size_t)(0*2 + ntile)*8 + chunk) * 32768) + sw) = H;
        *(uint2*)(g_B + (((size_t)(1*2 + ntile)*8 + chunk) * 32768) + sw) = L;
    }
}

// ===========================================================================
// Kernel 3: out = x @ R via mma.sync (HMMA), bf16 3-split, fp32 accumulate.
// CTA 128x256, 8 warps (2m x 4n), warp tile 64x64, K-chunk 64, 2 stages.
// ===========================================================================
#define A_HI_OFF 0
#define A_LO_OFF 16384
#define B_HI_OFF 32768
#define B_LO_OFF 65536
#define STAGE_BYTES 98304
#define GEMM_SMEM (1024 + 2 * STAGE_BYTES)

__device__ __forceinline__ void ldsm4(uint32_t* r, uint32_t addr) {
    asm volatile("ldmatrix.sync.aligned.m8n8.x4.shared.b16 {%0,%1,%2,%3}, [%4];"
        : "=r"(r[0]), "=r"(r[1]), "=r"(r[2]), "=r"(r[3]) : "r"(addr));
}
__device__ __forceinline__ void mma16816(float* c, const uint32_t* a,
                                         uint32_t b0, uint32_t b1) {
    asm volatile(
        "mma.sync.aligned.m16n8k16.row.col.f32.bf16.bf16.f32 "
        "{%0,%1,%2,%3}, {%4,%5,%6,%7}, {%8,%9}, {%0,%1,%2,%3};"
        : "+f"(c[0]), "+f"(c[1]), "+f"(c[2]), "+f"(c[3])
        : "r"(a[0]), "r"(a[1]), "r"(a[2]), "r"(a[3]), "r"(b0), "r"(b1));
}
__device__ __forceinline__ void cpasync16(uint32_t dst, const void* src) {
    asm volatile("cp.async.cg.shared.global [%0], [%1], 16;"
        :: "r"(dst), "l"(src) : "memory");
}
#define CP_COMMIT() asm volatile("cp.async.commit_group;" ::: "memory")
#define CP_WAIT(n)  asm volatile("cp.async.wait_group %0;" :: "n"(n) : "memory")

__device__ __forceinline__ void split8(const float* s, uint4& h, uint4& l) {
    uint32_t hh[4], ll[4];
    #pragma unroll
    for (int p = 0; p < 4; ++p) {
        float a = s[2*p], b = s[2*p+1];
        __nv_bfloat16 ha = __float2bfloat16(a);
        __nv_bfloat16 hb = __float2bfloat16(b);
        float ra = a - __bfloat162float(ha);
        float rb = b - __bfloat162float(hb);
        __nv_bfloat162 hp = __halves2bfloat162(ha, hb);
        __nv_bfloat162 lp = __floats2bfloat162_rn(ra, rb);
        hh[p] = *(uint32_t*)&hp;
        ll[p] = *(uint32_t*)&lp;
    }
    h = make_uint4(hh[0], hh[1], hh[2], hh[3]);
    l = make_uint4(ll[0], ll[1], ll[2], ll[3]);
}

__global__ __launch_bounds__(256, 1) void gemm_mma_kernel(const float* __restrict__ x,
                                                          float* __restrict__ out) {
    extern __shared__ char dsm[];
    char* smp = (char*)(((uintptr_t)dsm + 1023) & ~(uintptr_t)1023);
    const uint32_t sb = smem_u32(smp);

    const int tid = threadIdx.x;
    const int wid = tid >> 5;
    const int lane = tid & 31;
    const int wm = wid & 1;          // 0..1 -> m offset wm*64
    const int wn = wid >> 1;         // 0..3 -> n offset wn*64
    const int nt = blockIdx.x;       // 0..1
    const int bm = blockIdx.y << 7;

    float c[4][8][4];
    #pragma unroll
    for (int i = 0; i < 4; ++i)
        #pragma unroll
        for (int jj = 0; jj < 8; ++jj)
            #pragma unroll
            for (int q = 0; q < 4; ++q) c[i][jj][q] = 0.f;

    const int arow = tid >> 1;
    const int ahalf = tid & 1;
    const float4* xrow = (const float4*)(x + (size_t)(bm + arow) * SDIM) + ahalf * 8;

    // prologue: x regs for chunk 0; cp.async B chunk 0 -> stage 0
    float4 xr[8];
    #pragma unroll
    for (int p = 0; p < 8; ++p) xr[p] = xrow[p];   // chunk 0 = k[0:64)
    {
        const char* srcH = (const char*)(g_B + (((size_t)(0*2 + nt)*8 + 0) * 32768)) + tid * 16;
        const char* srcL = (const char*)(g_B + (((size_t)(1*2 + nt)*8 + 0) * 32768)) + tid * 16;
        #pragma unroll
        for (int i = 0; i < 8; ++i) {
            cpasync16(sb + B_HI_OFF + tid * 16 + i * 4096, srcH + i * 4096);
            cpasync16(sb + B_LO_OFF + tid * 16 + i * 4096, srcL + i * 4096);
        }
        CP_COMMIT();
    }

    for (int kc = 0; kc < 8; ++kc) {
        const uint32_t st = sb + (kc & 1) * STAGE_BYTES;
        __syncthreads();   // stage (kc&1) free of previous readers

        // --- STS A (convert xr -> bf16 hi/lo, swizzled) ---
        {
            char* ah = smp + (st - sb) + A_HI_OFF;
            char* al = smp + (st - sb) + A_LO_OFF;
            #pragma unroll
            for (int p = 0; p < 4; ++p) {
                float s[8] = {xr[2*p].x, xr[2*p].y, xr[2*p].z, xr[2*p].w,
                              xr[2*p+1].x, xr[2*p+1].y, xr[2*p+1].z, xr[2*p+1].w};
                uint4 h, l;
                split8(s, h, l);
                const unsigned off = (unsigned)arow * 128u + (unsigned)ahalf * 64u + (unsigned)p * 16u;
                const unsigned sw = SW128(off);
                *(uint4*)(ah + sw) = h;
                *(uint4*)(al + sw) = l;
            }
        }

        // --- prefetch next chunk: x regs + cp.async B ---
        if (kc < 7) {
            const float4* xn = xrow + (kc + 1) * 16;
            #pragma unroll
            for (int p = 0; p < 8; ++p) xr[p] = xn[p];
            const uint32_t st2 = sb + ((kc + 1) & 1) * STAGE_BYTES;
            const char* srcH = (const char*)(g_B + (((size_t)(0*2 + nt)*8 + (kc+1)) * 32768)) + tid * 16;
            const char* srcL = (const char*)(g_B + (((size_t)(1*2 + nt)*8 + (kc+1)) * 32768)) + tid * 16;
            #pragma unroll
            for (int i = 0; i < 8; ++i) {
                cpasync16(st2 + B_HI_OFF + tid * 16 + i * 4096, srcH + i * 4096);
                cpasync16(st2 + B_LO_OFF + tid * 16 + i * 4096, srcL + i * 4096);
            }
            CP_COMMIT();
            CP_WAIT(1);
        } else {
            CP_WAIT(0);
        }
        __syncthreads();

        // --- compute chunk (64 k) ---
        const int la = lane & 15;
        const int lh = lane >> 4;
        #pragma unroll
        for (int ks = 0; ks < 4; ++ks) {
            uint32_t ah[4][4], bb[4][4], t[4][4];
            // A hi frags: 4 m-tiles
            #pragma unroll
            for (int mt = 0; mt < 4; ++mt) {
                const unsigned off = (unsigned)(wm*64 + mt*16 + la) * 128u
                                   + (unsigned)((lh*8 + ks*16) * 2);
                ldsm4(ah[mt], st + A_HI_OFF + SW128(off));
            }
            // B hi frags: 4 n-pairs
            #pragma unroll
            for (int np = 0; np < 4; ++np) {
                const unsigned off = (unsigned)(wn*64 + np*16 + la) * 128u
                                   + (unsigned)((lh*8 + ks*16) * 2);
                ldsm4(bb[np], st + B_HI_OFF + SW128(off));
            }
            #pragma unroll
            for (int mt = 0; mt < 4; ++mt)
                #pragma unroll
                for (int np = 0; np < 4; ++np) {
                    mma16816(c[mt][2*np],   ah[mt], bb[np][0], bb[np][2]);
                    mma16816(c[mt][2*np+1], ah[mt], bb[np][1], bb[np][3]);
                }
            // A lo x B hi
            #pragma unroll
            for (int mt = 0; mt < 4; ++mt) {
                const unsigned off = (unsigned)(wm*64 + mt*16 + la) * 128u
                                   + (unsigned)((lh*8 + ks*16) * 2);
                ldsm4(t[mt], st + A_LO_OFF + SW128(off));
            }
            #pragma unroll
            for (int mt = 0; mt < 4; ++mt)
                #pragma unroll
                for (int np = 0; np < 4; ++np) {
                    mma16816(c[mt][2*np],   t[mt], bb[np][0], bb[np][2]);
                    mma16816(c[mt][2*np+1], t[mt], bb[np][1], bb[np][3]);
                }
            // A hi x B lo (overwrite bb)
            #pragma unroll
            for (int np = 0; np < 4; ++np) {
                const unsigned off = (unsigned)(wn*64 + np*16 + la) * 128u
                                   + (unsigned)((lh*8 + ks*16) * 2);
                ldsm4(bb[np], st + B_LO_OFF + SW128(off));
            }
            #pragma unroll
            for (int mt = 0; mt < 4; ++mt)
                #pragma unroll
                for (int np = 0; np < 4; ++np) {
                    mma16816(c[mt][2*np],   ah[mt], bb[np][0], bb[np][2]);
                    mma16816(c[mt][2*np+1], ah[mt], bb[np][1], bb[np][3]);
                }
        }
    }

    // --- epilogue: direct STG (float2 per fragment half) ---
    const int r0 = bm + wm * 64 + (lane >> 2);
    const int c0 = (nt << 8) + wn * 64 + (lane & 3) * 2;
    #pragma unroll
    for (int mt = 0; mt < 4; ++mt) {
        #pragma unroll
        for (int ntile = 0; ntile < 8; ++ntile) {
            float* p0 = out + (size_t)(r0 + mt*16)     * SDIM + c0 + ntile*8;
            float* p1 = out + (size_t)(r0 + mt*16 + 8) * SDIM + c0 + ntile*8;
            *(float2*)p0 = make_float2(c[mt][ntile][0], c[mt][ntile][1]);
            *(float2*)p1 = make_float2(c[mt][ntile][2], c[mt][ntile][3]);
        }
    }
}

// ===========================================================================
extern "C" void kernel_launch(void* const* d_in, const int* in_sizes, int n_in,
                              void* d_out, int out_size) {
    const float* x = (const float*)d_in[0];   // [65536, 512]
    const float* v = (const float*)d_in[1];   // [514, 512, 1]
    float* out = (float*)d_out;               // [65536, 512]

    cudaFuncSetAttribute(gemm_mma_kernel, cudaFuncAttributeMaxDynamicSharedMemorySize, GEMM_SMEM);

    compute_c_kernel<<<NV, 128>>>(v);
    build_R_kernel<<<SDIM * 32 / 256, 256>>>(v);
    dim3 grid(2, MROWS / 128);
    gemm_mma_kernel<<<grid, 256, GEMM_SMEM>>>(x, out);
}

// round 4
// speedup vs baseline: 2.8677x; 1.6721x over previous
#include <cuda_runtime.h>
#include <cuda_bf16.h>
#include <cuda_fp16.h>
#include <cstdint>

#define NV    514
#define SDIM  512
#define MROWS 65536
#define EPSF  1e-16f

// ---------------------------------------------------------------------------
// Device scratch. g_B holds R^T rows (= R columns) as fp16, PRE-SWIZZLED
// SMEM tile images: [ntile(2)][chunk(8)] blocks of 32768 B; each block is a
// 256(n-rows) x 64(k) fp16 tile, 128 B/row, SW128-swizzled.
// ---------------------------------------------------------------------------
__device__ __align__(16) unsigned char g_B[2 * 8 * 32768];
__device__ float g_c[NV];

#define SW128(b) ((b) ^ (((b) >> 3) & 0x70))

__device__ __forceinline__ uint32_t smem_u32(const void* p) {
    uint32_t a;
    asm("{ .reg .u64 t; cvta.to.shared.u64 t, %1; cvt.u32.u64 %0, t; }"
        : "=r"(a) : "l"(p));
    return a;
}

// ===========================================================================
// Kernel 1: c_k = 2 / (||v_k||^2 + eps)
// ===========================================================================
__global__ void compute_c_kernel(const float* __restrict__ v) {
    const int k = blockIdx.x;
    const int t = threadIdx.x;
    const float* vk = v + k * SDIM;
    float s = 0.f;
    for (int i = t; i < SDIM; i += 128) { float a = vk[i]; s = fmaf(a, a, s); }
    #pragma unroll
    for (int o = 16; o > 0; o >>= 1) s += __shfl_xor_sync(0xffffffffu, s, o);
    __shared__ float red[4];
    if ((t & 31) == 0) red[t >> 5] = s;
    __syncthreads();
    if (t == 0) g_c[k] = 2.0f / (red[0] + red[1] + red[2] + red[3] + EPSF);
}

// ===========================================================================
// Kernel 2: reflector chain -> rows of R^T, emitted as fp16 into the
// pre-swizzled tile layout of g_B. One warp per column j.
// ===========================================================================
__global__ __launch_bounds__(256) void build_R_kernel(const float* __restrict__ v) {
    __shared__ float sc[NV];
    for (int i = threadIdx.x; i < NV; i += blockDim.x) sc[i] = g_c[i];
    __syncthreads();

    const int warp = (blockIdx.x * blockDim.x + threadIdx.x) >> 5;
    const int lane = threadIdx.x & 31;
    if (warp >= SDIM) return;
    const int j = warp;

    float r[16];
    #pragma unroll
    for (int i = 0; i < 16; ++i) r[i] = 0.f;
    {
        const int m = j >> 7;
        if (lane == ((j & 127) >> 2)) r[m * 4 + (j & 3)] = 1.0f;
    }

    const float4* v4 = (const float4*)v;
    float a[16], an[16];
    #pragma unroll
    for (int m = 0; m < 4; ++m) {
        float4 t = v4[m * 32 + lane];
        a[m*4+0]=t.x; a[m*4+1]=t.y; a[m*4+2]=t.z; a[m*4+3]=t.w;
    }

    for (int k = 0; k < NV; ++k) {
        float d0 = 0.f, d1 = 0.f, d2 = 0.f, d3 = 0.f;
        #pragma unroll
        for (int q = 0; q < 4; ++q) {
            d0 = fmaf(a[0*4+q], r[0*4+q], d0);
            d1 = fmaf(a[1*4+q], r[1*4+q], d1);
            d2 = fmaf(a[2*4+q], r[2*4+q], d2);
            d3 = fmaf(a[3*4+q], r[3*4+q], d3);
        }
        if (k + 1 < NV) {
            const float4* vn = v4 + (size_t)(k + 1) * 128;
            #pragma unroll
            for (int m = 0; m < 4; ++m) {
                float4 t = vn[m * 32 + lane];
                an[m*4+0]=t.x; an[m*4+1]=t.y; an[m*4+2]=t.z; an[m*4+3]=t.w;
            }
        }
        float d = (d0 + d1) + (d2 + d3);
        #pragma unroll
        for (int o = 16; o > 0; o >>= 1) d += __shfl_xor_sync(0xffffffffu, d, o);

        const float t = d * sc[k];
        #pragma unroll
        for (int i = 0; i < 16; ++i) r[i] = fmaf(-t, a[i], r[i]);
        #pragma unroll
        for (int i = 0; i < 16; ++i) a[i] = an[i];
    }

    const int ntile = j >> 8;
    const unsigned rowb = (unsigned)(j & 255) * 128u;
    #pragma unroll
    for (int m = 0; m < 4; ++m) {
        const int k0 = m * 128 + lane * 4;
        const int chunk = k0 >> 6;
        const unsigned off = rowb + (unsigned)((k0 & 63) * 2);
        const unsigned sw = SW128(off);

        __half2 p0 = __floats2half2_rn(r[m*4+0], r[m*4+1]);
        __half2 p1 = __floats2half2_rn(r[m*4+2], r[m*4+3]);
        uint2 H = make_uint2(*(uint32_t*)&p0, *(uint32_t*)&p1);
        *(uint2*)(g_B + (((size_t)ntile*8 + chunk) * 32768) + sw) = H;
    }
}

// ===========================================================================
// Kernel 3: out = x @ R via mma.sync fp16 (fp32 accumulate), single pass.
// CTA 128x256, 8 warps (2m x 4n), warp tile 64x64, K-chunk 64, 2 stages.
// ===========================================================================
#define A_OFF 0
#define B_OFF 16384
#define STAGE_BYTES 49152
#define GEMM_SMEM (1024 + 2 * STAGE_BYTES)

__device__ __forceinline__ void ldsm4(uint32_t* r, uint32_t addr) {
    asm volatile("ldmatrix.sync.aligned.m8n8.x4.shared.b16 {%0,%1,%2,%3}, [%4];"
        : "=r"(r[0]), "=r"(r[1]), "=r"(r[2]), "=r"(r[3]) : "r"(addr));
}
__device__ __forceinline__ void mma16816(float* c, const uint32_t* a,
                                         uint32_t b0, uint32_t b1) {
    asm volatile(
        "mma.sync.aligned.m16n8k16.row.col.f32.f16.f16.f32 "
        "{%0,%1,%2,%3}, {%4,%5,%6,%7}, {%8,%9}, {%0,%1,%2,%3};"
        : "+f"(c[0]), "+f"(c[1]), "+f"(c[2]), "+f"(c[3])
        : "r"(a[0]), "r"(a[1]), "r"(a[2]), "r"(a[3]), "r"(b0), "r"(b1));
}
__device__ __forceinline__ void cpasync16(uint32_t dst, const void* src) {
    asm volatile("cp.async.cg.shared.global [%0], [%1], 16;"
        :: "r"(dst), "l"(src) : "memory");
}
#define CP_COMMIT() asm volatile("cp.async.commit_group;" ::: "memory")
#define CP_WAIT(n)  asm volatile("cp.async.wait_group %0;" :: "n"(n) : "memory")

__global__ __launch_bounds__(256, 1) void gemm_mma_kernel(const float* __restrict__ x,
                                                          float* __restrict__ out) {
    extern __shared__ char dsm[];
    char* smp = (char*)(((uintptr_t)dsm + 1023) & ~(uintptr_t)1023);
    const uint32_t sb = smem_u32(smp);

    const int tid = threadIdx.x;
    const int wid = tid >> 5;
    const int lane = tid & 31;
    const int wm = wid & 1;          // m offset wm*64
    const int wn = wid >> 1;         // n offset wn*64
    const int nt = blockIdx.x;       // 0..1
    const int bm = blockIdx.y << 7;

    float c[4][8][4];
    #pragma unroll
    for (int i = 0; i < 4; ++i)
        #pragma unroll
        for (int jj = 0; jj < 8; ++jj)
            #pragma unroll
            for (int q = 0; q < 4; ++q) c[i][jj][q] = 0.f;

    const int arow = tid >> 1;
    const int ahalf = tid & 1;
    const float4* xrow = (const float4*)(x + (size_t)(bm + arow) * SDIM) + ahalf * 8;

    // prologue: x regs chunk 0; cp.async B chunk 0 -> stage 0
    float4 xr[8];
    #pragma unroll
    for (int p = 0; p < 8; ++p) xr[p] = xrow[p];
    {
        const char* srcB = (const char*)(g_B + (((size_t)nt*8 + 0) * 32768)) + tid * 16;
        #pragma unroll
        for (int i = 0; i < 8; ++i)
            cpasync16(sb + B_OFF + tid * 16 + i * 4096, srcB + i * 4096);
        CP_COMMIT();
    }

    for (int kc = 0; kc < 8; ++kc) {
        const uint32_t st = sb + (kc & 1) * STAGE_BYTES;
        __syncthreads();   // stage (kc&1) free of previous readers

        // --- STS A (convert xr -> fp16, swizzled) ---
        {
            char* ab = smp + (st - sb) + A_OFF;
            #pragma unroll
            for (int p = 0; p < 4; ++p) {
                float4 fa = xr[2*p], fb = xr[2*p+1];
                __half2 h0 = __floats2half2_rn(fa.x, fa.y);
                __half2 h1 = __floats2half2_rn(fa.z, fa.w);
                __half2 h2 = __floats2half2_rn(fb.x, fb.y);
                __half2 h3 = __floats2half2_rn(fb.z, fb.w);
                uint4 h = make_uint4(*(uint32_t*)&h0, *(uint32_t*)&h1,
                                     *(uint32_t*)&h2, *(uint32_t*)&h3);
                const unsigned off = (unsigned)arow * 128u + (unsigned)ahalf * 64u + (unsigned)p * 16u;
                *(uint4*)(ab + SW128(off)) = h;
            }
        }

        // --- prefetch next chunk: x regs + cp.async B ---
        if (kc < 7) {
            const float4* xn = xrow + (kc + 1) * 16;
            #pragma unroll
            for (int p = 0; p < 8; ++p) xr[p] = xn[p];
            const uint32_t st2 = sb + ((kc + 1) & 1) * STAGE_BYTES;
            const char* srcB = (const char*)(g_B + (((size_t)nt*8 + (kc+1)) * 32768)) + tid * 16;
            #pragma unroll
            for (int i = 0; i < 8; ++i)
                cpasync16(st2 + B_OFF + tid * 16 + i * 4096, srcB + i * 4096);
            CP_COMMIT();
            CP_WAIT(1);
        } else {
            CP_WAIT(0);
        }
        __syncthreads();

        // --- compute chunk (64 k) ---
        const int la = lane & 15;
        const int lh = lane >> 4;
        #pragma unroll
        for (int ks = 0; ks < 4; ++ks) {
            uint32_t af[4][4], bf[4][4];
            #pragma unroll
            for (int mt = 0; mt < 4; ++mt) {
                const unsigned off = (unsigned)(wm*64 + mt*16 + la) * 128u
                                   + (unsigned)((lh*8 + ks*16) * 2);
                ldsm4(af[mt], st + A_OFF + SW128(off));
            }
            #pragma unroll
            for (int np = 0; np < 4; ++np) {
                const unsigned off = (unsigned)(wn*64 + np*16 + la) * 128u
                                   + (unsigned)((lh*8 + ks*16) * 2);
                ldsm4(bf[np], st + B_OFF + SW128(off));
            }
            #pragma unroll
            for (int mt = 0; mt < 4; ++mt)
                #pragma unroll
                for (int np = 0; np < 4; ++np) {
                    mma16816(c[mt][2*np],   af[mt], bf[np][0], bf[np][2]);
                    mma16816(c[mt][2*np+1], af[mt], bf[np][1], bf[np][3]);
                }
        }
    }

    // --- epilogue: direct STG ---
    const int r0 = bm + wm * 64 + (lane >> 2);
    const int c0 = (nt << 8) + wn * 64 + (lane & 3) * 2;
    #pragma unroll
    for (int mt = 0; mt < 4; ++mt) {
        #pragma unroll
        for (int ntl = 0; ntl < 8; ++ntl) {
            float* p0 = out + (size_t)(r0 + mt*16)     * SDIM + c0 + ntl*8;
            float* p1 = out + (size_t)(r0 + mt*16 + 8) * SDIM + c0 + ntl*8;
            *(float2*)p0 = make_float2(c[mt][ntl][0], c[mt][ntl][1]);
            *(float2*)p1 = make_float2(c[mt][ntl][2], c[mt][ntl][3]);
        }
    }
}

// ===========================================================================
extern "C" void kernel_launch(void* const* d_in, const int* in_sizes, int n_in,
                              void* d_out, int out_size) {
    const float* x = (const float*)d_in[0];   // [65536, 512]
    const float* v = (const float*)d_in[1];   // [514, 512, 1]
    float* out = (float*)d_out;               // [65536, 512]

    cudaFuncSetAttribute(gemm_mma_kernel, cudaFuncAttributeMaxDynamicSharedMemorySize, GEMM_SMEM);

    compute_c_kernel<<<NV, 128>>>(v);
    build_R_kernel<<<SDIM * 32 / 256, 256>>>(v);
    dim3 grid(2, MROWS / 128);
    gemm_mma_kernel<<<grid, 256, GEMM_SMEM>>>(x, out);
}